// round 3
// baseline (speedup 1.0000x reference)
#include <cuda_runtime.h>

#define N_NODES 50000
#define N_EDGES 800000
#define IN_CH 16
#define OUT_CH 16
#define HID 100
#define EPW 4      // edges per warp per iteration
#define WARPS 4    // warps per block
#define THREADS (WARPS*32)

// Shared layout (floats):
//  sW1: 800, sB1: 100, sW2: 10000, sB2: 100, sW3: 10000, sB3: 100, sW4: 25600, sB4: 256
//  = 46956 floats of weights, then per-warp scratch of 1936 floats
#define W_FLOATS 46956
#define SCR_FLOATS 1936
#define SMEM_FLOATS (W_FLOATS + WARPS*SCR_FLOATS)
#define SMEM_BYTES (SMEM_FLOATS*4)

__device__ float g_agg[N_NODES*OUT_CH];
__device__ float g_cnt[N_NODES];

__global__ void zero_kernel() {
    int total = N_NODES*OUT_CH;
    for (int i = blockIdx.x*blockDim.x + threadIdx.x; i < total; i += gridDim.x*blockDim.x) {
        g_agg[i] = 0.0f;
        if (i < N_NODES) g_cnt[i] = 0.0f;
    }
}

// One hidden->hidden (or attr->hidden) layer for 4 edges at once.
// lanes 0..24 each own 4 contiguous output columns (float4 weight loads, conflict-free).
__device__ __forceinline__ void mlp_layer(const float* __restrict__ sW, const float* __restrict__ sB,
                                          const float* __restrict__ hin, float* __restrict__ hout,
                                          int lane, int kdim, int hstride) {
    if (lane < 25) {
        const int j0 = lane * 4;
        float4 acc[EPW];
        float4 bb = *(const float4*)&sB[j0];
        #pragma unroll
        for (int e = 0; e < EPW; e++) acc[e] = bb;
        #pragma unroll 4
        for (int k = 0; k < kdim; k++) {
            float4 w = *(const float4*)&sW[k*HID + j0];
            #pragma unroll
            for (int e = 0; e < EPW; e++) {
                float h = hin[e*hstride + k];
                acc[e].x += h * w.x;
                acc[e].y += h * w.y;
                acc[e].z += h * w.z;
                acc[e].w += h * w.w;
            }
        }
        #pragma unroll
        for (int e = 0; e < EPW; e++) {
            hout[e*HID + j0 + 0] = fmaxf(acc[e].x, 0.0f);
            hout[e*HID + j0 + 1] = fmaxf(acc[e].y, 0.0f);
            hout[e*HID + j0 + 2] = fmaxf(acc[e].z, 0.0f);
            hout[e*HID + j0 + 3] = fmaxf(acc[e].w, 0.0f);
        }
    }
    __syncwarp();
}

extern __shared__ float smem[];

__global__ void __launch_bounds__(THREADS, 1)
edge_kernel(const float* __restrict__ x,
            const int* __restrict__ ei,
            const float* __restrict__ ea,
            const float* __restrict__ W1, const float* __restrict__ b1,
            const float* __restrict__ W2, const float* __restrict__ b2,
            const float* __restrict__ W3, const float* __restrict__ b3,
            const float* __restrict__ W4, const float* __restrict__ b4)
{
    float* sW1 = smem;                 // 800
    float* sB1 = sW1 + 800;            // 100
    float* sW2 = sB1 + 100;            // 10000
    float* sB2 = sW2 + 10000;          // 100
    float* sW3 = sB2 + 100;            // 10000
    float* sB3 = sW3 + 10000;          // 100
    float* sW4 = sB3 + 100;            // 25600
    float* sB4 = sW4 + 25600;          // 256
    float* sScr = sB4 + 256;

    const int tid = threadIdx.x;
    // cooperative weight copy
    for (int i = tid; i < 800;   i += THREADS) sW1[i] = W1[i];
    for (int i = tid; i < 100;   i += THREADS) sB1[i] = b1[i];
    for (int i = tid; i < 10000; i += THREADS) sW2[i] = W2[i];
    for (int i = tid; i < 100;   i += THREADS) sB2[i] = b2[i];
    for (int i = tid; i < 10000; i += THREADS) sW3[i] = W3[i];
    for (int i = tid; i < 100;   i += THREADS) sB3[i] = b3[i];
    for (int i = tid; i < 25600; i += THREADS) sW4[i] = W4[i];
    for (int i = tid; i < 256;   i += THREADS) sB4[i] = b4[i];
    __syncthreads();

    const int wid  = tid >> 5;
    const int lane = tid & 31;
    float* sw = sScr + wid * SCR_FLOATS;
    float* h0 = sw;            // 400
    float* h1 = sw + 400;      // 400
    float* wm = sw + 800;      // 1024
    float* xv = sw + 1824;     // 64
    float* av = sw + 1888;     // 32
    int*   sd = (int*)(sw + 1920); // src[4], dst[4]

    const int gwarp = blockIdx.x * WARPS + wid;
    const int nwarp = gridDim.x * WARPS;

    for (int base = gwarp * EPW; base < N_EDGES; base += nwarp * EPW) {
        // edge indices: edge_index is int32 (JAX default x64-disabled downcasts int64)
        if (lane < EPW) {
            sd[lane]       = ei[base + lane];            // src
            sd[EPW + lane] = ei[N_EDGES + base + lane];  // dst
        }
        // edge attrs: 4 edges x 8 = 32 values, coalesced
        {
            int e = lane >> 3, k = lane & 7;
            av[lane] = ea[(long)(base + e) * 8 + k];
        }
        __syncwarp();
        // gather x[src]: 4 edges x 16 = 64 values
        #pragma unroll
        for (int r = 0; r < 2; r++) {
            int idx = lane + 32*r;
            int e = idx >> 4, i = idx & 15;
            xv[idx] = x[(long)sd[e] * IN_CH + i];
        }
        __syncwarp();

        mlp_layer(sW1, sB1, av, h0, lane, 8,   8);    // 8  -> 100
        mlp_layer(sW2, sB2, h0, h1, lane, HID, HID);  // 100-> 100
        mlp_layer(sW3, sB3, h1, h0, lane, HID, HID);  // 100-> 100

        // layer 4: 100 -> 256, all 32 lanes, col = lane + 32*m (conflict-free scalar LDS)
        {
            float acc[EPW][8];
            #pragma unroll
            for (int m = 0; m < 8; m++) {
                float bb = sB4[lane + 32*m];
                #pragma unroll
                for (int e = 0; e < EPW; e++) acc[e][m] = bb;
            }
            #pragma unroll 2
            for (int k = 0; k < HID; k++) {
                float w[8];
                #pragma unroll
                for (int m = 0; m < 8; m++) w[m] = sW4[k*256 + lane + 32*m];
                #pragma unroll
                for (int e = 0; e < EPW; e++) {
                    float h = h0[e*HID + k];
                    #pragma unroll
                    for (int m = 0; m < 8; m++) acc[e][m] += h * w[m];
                }
            }
            #pragma unroll
            for (int e = 0; e < EPW; e++)
                #pragma unroll
                for (int m = 0; m < 8; m++)
                    wm[e*256 + lane + 32*m] = acc[e][m];
        }
        __syncwarp();

        // msg[e][o] = sum_i xv[e][i] * wm[e][i*16+o], scatter-add
        #pragma unroll
        for (int r = 0; r < 2; r++) {
            int idx = lane + 32*r;
            int e = idx >> 4, o = idx & 15;
            float m = 0.0f;
            #pragma unroll
            for (int i = 0; i < IN_CH; i++)
                m += xv[e*IN_CH + i] * wm[e*256 + i*16 + o];
            atomicAdd(&g_agg[(long)sd[EPW + e] * OUT_CH + o], m);
        }
        if (lane < EPW) atomicAdd(&g_cnt[sd[EPW + lane]], 1.0f);
        __syncwarp();  // protect shared scratch before next iteration
    }
}

__global__ void finalize_kernel(const float* __restrict__ x,
                                const float* __restrict__ root,
                                const float* __restrict__ bias,
                                float* __restrict__ out)
{
    int i = blockIdx.x*blockDim.x + threadIdx.x;
    if (i >= N_NODES*OUT_CH) return;
    int n = i >> 4, o = i & 15;
    float c = fmaxf(g_cnt[n], 1.0f);
    float acc = g_agg[i] / c + bias[o];
    const float* xr = x + (long)n * IN_CH;
    #pragma unroll
    for (int k = 0; k < IN_CH; k++)
        acc += xr[k] * root[k*OUT_CH + o];
    out[i] = acc;
}

extern "C" void kernel_launch(void* const* d_in, const int* in_sizes, int n_in,
                              void* d_out, int out_size) {
    const float* x    = (const float*)d_in[0];
    const int*   ei   = (const int*)d_in[1];
    const float* ea   = (const float*)d_in[2];
    const float* W1   = (const float*)d_in[3];
    const float* b1   = (const float*)d_in[4];
    const float* W2   = (const float*)d_in[5];
    const float* b2   = (const float*)d_in[6];
    const float* W3   = (const float*)d_in[7];
    const float* b3   = (const float*)d_in[8];
    const float* W4   = (const float*)d_in[9];
    const float* b4   = (const float*)d_in[10];
    const float* root = (const float*)d_in[11];
    const float* bias = (const float*)d_in[12];
    float* out = (float*)d_out;

    cudaFuncSetAttribute(edge_kernel, cudaFuncAttributeMaxDynamicSharedMemorySize, SMEM_BYTES);

    zero_kernel<<<1024, 256>>>();
    edge_kernel<<<1184, THREADS, SMEM_BYTES>>>(x, ei, ea, W1, b1, W2, b2, W3, b3, W4, b4);
    finalize_kernel<<<(N_NODES*OUT_CH + 255)/256, 256>>>(x, root, bias, out);
}

// round 4
// speedup vs baseline: 1.8256x; 1.8256x over previous
#include <cuda_runtime.h>
#include <cstdint>

#define N_NODES 50000
#define N_EDGES 800000
#define IN_CH 16
#define OUT_CH 16
#define M_TILE 32
#define NT_TILES (N_EDGES / M_TILE)   // 25000
#define THREADS 128

// ---- shared memory layout (floats) ----
// W1p [8][104]      @ 0       (832)
// W2p [100][104]    @ 832     (10400)
// W3p [100][104]    @ 11232   (10400)
// W4p [100][264]    @ 21632   (26400)   (stride 264 -> bank-conflict-free B frags)
// b1p [104]         @ 48032
// b2p [104]         @ 48136
// b3p [104]         @ 48240
// b4p [256]         @ 48344
// H1  [32][104]     @ 48600   (3328)
// H2  [32][104]     @ 51928   (3328)
// A0  [32][8]       @ 55256   (256)
// XV  [32][16]      @ 55512   (512)
// MSG [32][16]      @ 56024   (512)
// IDX [64] (int)    @ 56536
#define OFF_W1 0
#define OFF_W2 832
#define OFF_W3 11232
#define OFF_W4 21632
#define OFF_B1 48032
#define OFF_B2 48136
#define OFF_B3 48240
#define OFF_B4 48344
#define OFF_H1 48600
#define OFF_H2 51928
#define OFF_A0 55256
#define OFF_XV 55512
#define OFF_MSG 56024
#define OFF_IDX 56536
#define SMEM_FLOATS 56600
#define SMEM_BYTES (SMEM_FLOATS * 4)

__device__ float g_agg[N_NODES * OUT_CH];
__device__ float g_cnt[N_NODES];

__global__ void zero_kernel() {
    int total = N_NODES * OUT_CH;
    for (int i = blockIdx.x * blockDim.x + threadIdx.x; i < total; i += gridDim.x * blockDim.x) {
        g_agg[i] = 0.0f;
        if (i < N_NODES) g_cnt[i] = 0.0f;
    }
}

__device__ __forceinline__ float f2tf32(float x) {
    uint32_t u;
    asm("cvt.rna.tf32.f32 %0, %1;" : "=r"(u) : "f"(x));
    return __uint_as_float(u);
}

__device__ __forceinline__ void mma_k8(float& c0, float& c1, float& c2, float& c3,
                                       float a0, float a1, float a2, float a3,
                                       float b0, float b1) {
    asm volatile(
        "mma.sync.aligned.m16n8k8.row.col.f32.tf32.tf32.f32 "
        "{%0,%1,%2,%3},{%4,%5,%6,%7},{%8,%9},{%0,%1,%2,%3};\n"
        : "+f"(c0), "+f"(c1), "+f"(c2), "+f"(c3)
        : "r"(__float_as_uint(a0)), "r"(__float_as_uint(a1)),
          "r"(__float_as_uint(a2)), "r"(__float_as_uint(a3)),
          "r"(__float_as_uint(b0)), "r"(__float_as_uint(b1)));
}

__device__ __forceinline__ void mma_k4(float& c0, float& c1, float& c2, float& c3,
                                       float a0, float a1, float b0) {
    asm volatile(
        "mma.sync.aligned.m16n8k4.row.col.f32.tf32.tf32.f32 "
        "{%0,%1,%2,%3},{%4,%5},{%6},{%0,%1,%2,%3};\n"
        : "+f"(c0), "+f"(c1), "+f"(c2), "+f"(c3)
        : "r"(__float_as_uint(a0)), "r"(__float_as_uint(a1)),
          "r"(__float_as_uint(b0)));
}

// One MLP layer (with ReLU) on a 32-edge tile via tf32 mma.sync.
// Hin: [32][sin] fp32 in smem. Wp: [Ktot][sw] (zero-padded cols). Hout: [32][104].
// Warps split the n-tiles; processes 2 n-tiles x 2 m-tiles per k-step for 4-way MMA ILP.
__device__ __forceinline__ void layer_mma(const float* __restrict__ Hin, int sin, int Ktot,
                                          const float* __restrict__ Wp, int sw,
                                          const float* __restrict__ bp,
                                          float* __restrict__ Hout, int ntiles,
                                          int wid, int lane) {
    const int grp = lane >> 2, tig = lane & 3;
    const int k8 = Ktot >> 3, rem = Ktot & 7;

    for (int ntp = wid; ntp < ntiles; ntp += 8) {
        const bool has2 = (ntp + 4) < ntiles;
        const int n0 = ntp * 8;
        const int n1 = has2 ? (ntp + 4) * 8 : n0;

        float acc[2][2][4];  // [ntile][mtile][reg]
        {
            float ba0 = bp[n0 + 2 * tig], ba1 = bp[n0 + 2 * tig + 1];
            float bb0 = bp[n1 + 2 * tig], bb1 = bp[n1 + 2 * tig + 1];
            #pragma unroll
            for (int mt = 0; mt < 2; mt++) {
                acc[0][mt][0] = ba0; acc[0][mt][1] = ba1; acc[0][mt][2] = ba0; acc[0][mt][3] = ba1;
                acc[1][mt][0] = bb0; acc[1][mt][1] = bb1; acc[1][mt][2] = bb0; acc[1][mt][3] = bb1;
            }
        }

        for (int kt = 0; kt < k8; kt++) {
            const int k0 = kt * 8;
            float a[2][4];
            #pragma unroll
            for (int mt = 0; mt < 2; mt++) {
                const int r = mt * 16 + grp;
                a[mt][0] = Hin[r * sin + k0 + tig];
                a[mt][1] = Hin[(r + 8) * sin + k0 + tig];
                a[mt][2] = Hin[r * sin + k0 + tig + 4];
                a[mt][3] = Hin[(r + 8) * sin + k0 + tig + 4];
            }
            float b00 = Wp[(k0 + tig) * sw + n0 + grp];
            float b01 = Wp[(k0 + tig + 4) * sw + n0 + grp];
            float b10 = Wp[(k0 + tig) * sw + n1 + grp];
            float b11 = Wp[(k0 + tig + 4) * sw + n1 + grp];
            #pragma unroll
            for (int mt = 0; mt < 2; mt++) {
                mma_k8(acc[0][mt][0], acc[0][mt][1], acc[0][mt][2], acc[0][mt][3],
                       a[mt][0], a[mt][1], a[mt][2], a[mt][3], b00, b01);
                mma_k8(acc[1][mt][0], acc[1][mt][1], acc[1][mt][2], acc[1][mt][3],
                       a[mt][0], a[mt][1], a[mt][2], a[mt][3], b10, b11);
            }
        }
        if (rem) {  // k4 tail (Ktot=100 -> k 96..99)
            const int k0 = k8 * 8;
            #pragma unroll
            for (int mt = 0; mt < 2; mt++) {
                const int r = mt * 16 + grp;
                float a0 = Hin[r * sin + k0 + tig];
                float a1 = Hin[(r + 8) * sin + k0 + tig];
                float b0 = Wp[(k0 + tig) * sw + n0 + grp];
                float b1 = Wp[(k0 + tig) * sw + n1 + grp];
                mma_k4(acc[0][mt][0], acc[0][mt][1], acc[0][mt][2], acc[0][mt][3], a0, a1, b0);
                mma_k4(acc[1][mt][0], acc[1][mt][1], acc[1][mt][2], acc[1][mt][3], a0, a1, b1);
            }
        }

        // ReLU + store (float2, conflict-light)
        #pragma unroll
        for (int nt = 0; nt < 2; nt++) {
            if (nt == 1 && !has2) break;
            const int nb = (nt == 0) ? n0 : n1;
            #pragma unroll
            for (int mt = 0; mt < 2; mt++) {
                const int r = mt * 16 + grp;
                float2 v0 = make_float2(fmaxf(acc[nt][mt][0], 0.f), fmaxf(acc[nt][mt][1], 0.f));
                float2 v1 = make_float2(fmaxf(acc[nt][mt][2], 0.f), fmaxf(acc[nt][mt][3], 0.f));
                *(float2*)&Hout[r * 104 + nb + 2 * tig] = v0;
                *(float2*)&Hout[(r + 8) * 104 + nb + 2 * tig] = v1;
            }
        }
    }
}

// Layer 4 (100 -> 256, no ReLU) with fused einsum epilogue:
// D element at (edge e, col c) contributes XV[e][c>>4] * D to MSG[e][c&15].
__device__ __forceinline__ void layer4_mma(const float* __restrict__ Hin,
                                           const float* __restrict__ Wp,
                                           const float* __restrict__ bp,
                                           const float* __restrict__ XV,
                                           float* __restrict__ MSG,
                                           int wid, int lane) {
    const int grp = lane >> 2, tig = lane & 3;
    const int sw = 264;

    for (int ntp = wid; ntp < 32; ntp += 8) {
        const int n0 = ntp * 8;
        const int n1 = (ntp + 4) * 8;

        float acc[2][2][4];
        {
            float ba0 = bp[n0 + 2 * tig], ba1 = bp[n0 + 2 * tig + 1];
            float bb0 = bp[n1 + 2 * tig], bb1 = bp[n1 + 2 * tig + 1];
            #pragma unroll
            for (int mt = 0; mt < 2; mt++) {
                acc[0][mt][0] = ba0; acc[0][mt][1] = ba1; acc[0][mt][2] = ba0; acc[0][mt][3] = ba1;
                acc[1][mt][0] = bb0; acc[1][mt][1] = bb1; acc[1][mt][2] = bb0; acc[1][mt][3] = bb1;
            }
        }

        for (int kt = 0; kt < 12; kt++) {
            const int k0 = kt * 8;
            float a[2][4];
            #pragma unroll
            for (int mt = 0; mt < 2; mt++) {
                const int r = mt * 16 + grp;
                a[mt][0] = Hin[r * 104 + k0 + tig];
                a[mt][1] = Hin[(r + 8) * 104 + k0 + tig];
                a[mt][2] = Hin[r * 104 + k0 + tig + 4];
                a[mt][3] = Hin[(r + 8) * 104 + k0 + tig + 4];
            }
            float b00 = Wp[(k0 + tig) * sw + n0 + grp];
            float b01 = Wp[(k0 + tig + 4) * sw + n0 + grp];
            float b10 = Wp[(k0 + tig) * sw + n1 + grp];
            float b11 = Wp[(k0 + tig + 4) * sw + n1 + grp];
            #pragma unroll
            for (int mt = 0; mt < 2; mt++) {
                mma_k8(acc[0][mt][0], acc[0][mt][1], acc[0][mt][2], acc[0][mt][3],
                       a[mt][0], a[mt][1], a[mt][2], a[mt][3], b00, b01);
                mma_k8(acc[1][mt][0], acc[1][mt][1], acc[1][mt][2], acc[1][mt][3],
                       a[mt][0], a[mt][1], a[mt][2], a[mt][3], b10, b11);
            }
        }
        {   // k4 tail, k = 96..99
            const int k0 = 96;
            #pragma unroll
            for (int mt = 0; mt < 2; mt++) {
                const int r = mt * 16 + grp;
                float a0 = Hin[r * 104 + k0 + tig];
                float a1 = Hin[(r + 8) * 104 + k0 + tig];
                float b0 = Wp[(k0 + tig) * sw + n0 + grp];
                float b1 = Wp[(k0 + tig) * sw + n1 + grp];
                mma_k4(acc[0][mt][0], acc[0][mt][1], acc[0][mt][2], acc[0][mt][3], a0, a1, b0);
                mma_k4(acc[1][mt][0], acc[1][mt][1], acc[1][mt][2], acc[1][mt][3], a0, a1, b1);
            }
        }

        // fused einsum epilogue (col0 even -> col0, col0+1 share the same i)
        #pragma unroll
        for (int nt = 0; nt < 2; nt++) {
            const int nb = (nt == 0) ? n0 : n1;
            const int col0 = nb + 2 * tig;
            const int i = col0 >> 4;
            const int o = col0 & 15;
            #pragma unroll
            for (int mt = 0; mt < 2; mt++) {
                const int e0 = mt * 16 + grp;
                const int e1 = e0 + 8;
                float xv0 = XV[e0 * 16 + i];
                float xv1 = XV[e1 * 16 + i];
                atomicAdd(&MSG[e0 * 16 + o],     xv0 * acc[nt][mt][0]);
                atomicAdd(&MSG[e0 * 16 + o + 1], xv0 * acc[nt][mt][1]);
                atomicAdd(&MSG[e1 * 16 + o],     xv1 * acc[nt][mt][2]);
                atomicAdd(&MSG[e1 * 16 + o + 1], xv1 * acc[nt][mt][3]);
            }
        }
    }
}

extern __shared__ float smem[];

__global__ void __launch_bounds__(THREADS, 1)
edge_kernel(const float* __restrict__ x,
            const int* __restrict__ ei,
            const float* __restrict__ ea,
            const float* __restrict__ W1, const float* __restrict__ b1,
            const float* __restrict__ W2, const float* __restrict__ b2,
            const float* __restrict__ W3, const float* __restrict__ b3,
            const float* __restrict__ W4, const float* __restrict__ b4)
{
    const int tid = threadIdx.x;
    const int wid = tid >> 5, lane = tid & 31;

    float* W1p = smem + OFF_W1;
    float* W2p = smem + OFF_W2;
    float* W3p = smem + OFF_W3;
    float* W4p = smem + OFF_W4;
    float* b1p = smem + OFF_B1;
    float* b2p = smem + OFF_B2;
    float* b3p = smem + OFF_B3;
    float* b4p = smem + OFF_B4;
    float* H1  = smem + OFF_H1;
    float* H2  = smem + OFF_H2;
    float* A0  = smem + OFF_A0;
    float* XV  = smem + OFF_XV;
    float* MSG = smem + OFF_MSG;
    int*   sidx = (int*)(smem + OFF_IDX);
    int*   didx = sidx + 32;

    // ---- weight fill: zero-pad + pre-round to tf32 ----
    for (int i = tid; i < 8 * 104; i += THREADS) {
        int k = i / 104, j = i % 104;
        W1p[i] = (j < 100) ? f2tf32(W1[k * 100 + j]) : 0.0f;
    }
    for (int i = tid; i < 100 * 104; i += THREADS) {
        int k = i / 104, j = i % 104;
        W2p[i] = (j < 100) ? f2tf32(W2[k * 100 + j]) : 0.0f;
        W3p[i] = (j < 100) ? f2tf32(W3[k * 100 + j]) : 0.0f;
    }
    for (int i = tid; i < 100 * 264; i += THREADS) {
        int k = i / 264, j = i % 264;
        W4p[i] = (j < 256) ? f2tf32(W4[k * 256 + j]) : 0.0f;
    }
    for (int i = tid; i < 104; i += THREADS) {
        b1p[i] = (i < 100) ? b1[i] : 0.0f;
        b2p[i] = (i < 100) ? b2[i] : 0.0f;
        b3p[i] = (i < 100) ? b3[i] : 0.0f;
    }
    for (int i = tid; i < 256; i += THREADS) b4p[i] = b4[i];
    __syncthreads();

    for (int t = blockIdx.x; t < NT_TILES; t += gridDim.x) {
        const int base = t * M_TILE;

        if (tid < 32) {
            sidx[tid] = ei[base + tid];
            didx[tid] = ei[N_EDGES + base + tid];
        }
        for (int i = tid; i < 256; i += THREADS) A0[i] = ea[base * 8 + i];
        __syncthreads();

        for (int i = tid; i < 512; i += THREADS) {
            int e = i >> 4, c = i & 15;
            XV[i] = x[(long)sidx[e] * IN_CH + c];
        }
        for (int i = tid; i < 512; i += THREADS) MSG[i] = 0.0f;
        __syncthreads();

        layer_mma(A0, 8, 8,    W1p, 104, b1p, H1, 13, wid, lane);
        __syncthreads();
        layer_mma(H1, 104, 100, W2p, 104, b2p, H2, 13, wid, lane);
        __syncthreads();
        layer_mma(H2, 104, 100, W3p, 104, b3p, H1, 13, wid, lane);
        __syncthreads();
        layer4_mma(H1, W4p, b4p, XV, MSG, wid, lane);
        __syncthreads();

        for (int i = tid; i < 512; i += THREADS) {
            int e = i >> 4, o = i & 15;
            atomicAdd(&g_agg[(long)didx[e] * OUT_CH + o], MSG[i]);
        }
        if (tid < 32) atomicAdd(&g_cnt[didx[tid]], 1.0f);
        __syncthreads();  // protect smem buffers before next tile
    }
}

__global__ void finalize_kernel(const float* __restrict__ x,
                                const float* __restrict__ root,
                                const float* __restrict__ bias,
                                float* __restrict__ out)
{
    int i = blockIdx.x * blockDim.x + threadIdx.x;
    if (i >= N_NODES * OUT_CH) return;
    int n = i >> 4, o = i & 15;
    float c = fmaxf(g_cnt[n], 1.0f);
    float acc = g_agg[i] / c + bias[o];
    const float* xr = x + (long)n * IN_CH;
    #pragma unroll
    for (int k = 0; k < IN_CH; k++)
        acc += xr[k] * root[k * OUT_CH + o];
    out[i] = acc;
}

extern "C" void kernel_launch(void* const* d_in, const int* in_sizes, int n_in,
                              void* d_out, int out_size) {
    const float* x    = (const float*)d_in[0];
    const int*   ei   = (const int*)d_in[1];
    const float* ea   = (const float*)d_in[2];
    const float* W1   = (const float*)d_in[3];
    const float* b1   = (const float*)d_in[4];
    const float* W2   = (const float*)d_in[5];
    const float* b2   = (const float*)d_in[6];
    const float* W3   = (const float*)d_in[7];
    const float* b3   = (const float*)d_in[8];
    const float* W4   = (const float*)d_in[9];
    const float* b4   = (const float*)d_in[10];
    const float* root = (const float*)d_in[11];
    const float* bias = (const float*)d_in[12];
    float* out = (float*)d_out;

    cudaFuncSetAttribute(edge_kernel, cudaFuncAttributeMaxDynamicSharedMemorySize, SMEM_BYTES);

    zero_kernel<<<1024, 256>>>();
    edge_kernel<<<152, THREADS, SMEM_BYTES>>>(x, ei, ea, W1, b1, W2, b2, W3, b3, W4, b4);
    finalize_kernel<<<(N_NODES * OUT_CH + 255) / 256, 256>>>(x, root, bias, out);
}

// round 6
// speedup vs baseline: 3.6117x; 1.9783x over previous
#include <cuda_runtime.h>
#include <cuda_fp16.h>
#include <cstdint>

#define N_NODES 50000
#define N_EDGES 800000
#define IN_CH 16
#define OUT_CH 16
#define M_TILE 64
#define NT_TILES (N_EDGES / M_TILE)   // 12500
#define THREADS 256
#define GRID 152

// ---- smem byte offsets ----
#define SM_W1   0        // [16][120] f16   = 3840
#define SM_W2   3840     // [112][120] f16  = 26880
#define SM_W3   30720    // [112][120] f16  = 26880
#define SM_W4   57600    // [112][264] f16  = 59136
#define SM_A0   116736   // [64][24] f16    = 3072
#define SM_H1   119808   // [64][120] f16   = 15360
#define SM_H2   135168   // [64][120] f16   = 15360
#define SM_XV   150528   // [64][16] f32    = 4096
#define SM_MSG  154624   // [64][16] f32    = 4096
#define SM_B1   158720   // [112] f32
#define SM_B2   159168
#define SM_B3   159616
#define SM_B4   160064   // [256] f32
#define SM_IDX  161088   // dst [64] int
#define SM_SRC  161344   // src [64] int
#define SMEM_BYTES 161600
#define W_ZERO_U32 (116736 / 4)

__device__ float g_agg[N_NODES * OUT_CH];
__device__ float g_cnt[N_NODES];

__device__ __forceinline__ uint32_t smem_u32(const void* p) {
    uint32_t a;
    asm("{ .reg .u64 t; cvta.to.shared.u64 t, %1; cvt.u32.u64 %0, t; }" : "=r"(a) : "l"(p));
    return a;
}

#define LDSM_X4(r, a) \
    asm volatile("ldmatrix.sync.aligned.m8n8.x4.shared.b16 {%0,%1,%2,%3}, [%4];" \
        : "=r"((r)[0]), "=r"((r)[1]), "=r"((r)[2]), "=r"((r)[3]) : "r"(a))
#define LDSM_X2T(r, a) \
    asm volatile("ldmatrix.sync.aligned.m8n8.x2.trans.shared.b16 {%0,%1}, [%2];" \
        : "=r"((r)[0]), "=r"((r)[1]) : "r"(a))
#define MMA16816(c, a, b) \
    asm volatile("mma.sync.aligned.m16n8k16.row.col.f32.f16.f16.f32 " \
        "{%0,%1,%2,%3},{%4,%5,%6,%7},{%8,%9},{%0,%1,%2,%3};" \
        : "+f"((c)[0]), "+f"((c)[1]), "+f"((c)[2]), "+f"((c)[3]) \
        : "r"((a)[0]), "r"((a)[1]), "r"((a)[2]), "r"((a)[3]), "r"((b)[0]), "r"((b)[1]))

__global__ void zero_kernel() {
    int total = N_NODES * OUT_CH;
    for (int i = blockIdx.x * blockDim.x + threadIdx.x; i < total; i += gridDim.x * blockDim.x) {
        g_agg[i] = 0.0f;
        if (i < N_NODES) g_cnt[i] = 0.0f;
    }
}

// Generic MLP layer: Hout = relu(Hin @ W + b), fp16 in/out, f32 accum.
template<int KSTEPS, int MAXNT>
__device__ __forceinline__ void layer_f16(
    const __half* __restrict__ Hin, int sIn,
    const __half* __restrict__ W, int sW,
    const float* __restrict__ bias,
    __half* __restrict__ Hout, int sOut,
    int nt0, int ntCnt, int mbase, int lane)
{
    const int grp = lane >> 2, tig = lane & 3;
    float acc[MAXNT][2][4];
    #pragma unroll
    for (int nt = 0; nt < MAXNT; nt++) {
        if (nt >= ntCnt) break;
        const int c = (nt0 + nt) * 8 + 2 * tig;
        const float b0 = bias[c], b1 = bias[c + 1];
        #pragma unroll
        for (int mt = 0; mt < 2; mt++) {
            acc[nt][mt][0] = b0; acc[nt][mt][1] = b1;
            acc[nt][mt][2] = b0; acc[nt][mt][3] = b1;
        }
    }
    const int arow = mbase + ((lane >> 3) & 1) * 8 + (lane & 7);
    const int acol = (lane >> 4) * 8;
    const int brow = lane & 15;
    #pragma unroll
    for (int k = 0; k < KSTEPS; k++) {
        const int k0 = k * 16;
        uint32_t a[2][4];
        #pragma unroll
        for (int mt = 0; mt < 2; mt++) {
            uint32_t aaddr = smem_u32(Hin + (arow + mt * 16) * sIn + k0 + acol);
            LDSM_X4(a[mt], aaddr);
        }
        #pragma unroll
        for (int nt = 0; nt < MAXNT; nt++) {
            if (nt >= ntCnt) break;
            const int n0 = (nt0 + nt) * 8;
            uint32_t b[2];
            uint32_t baddr = smem_u32(W + (k0 + brow) * sW + n0);
            LDSM_X2T(b, baddr);
            MMA16816(acc[nt][0], a[0], b);
            MMA16816(acc[nt][1], a[1], b);
        }
    }
    #pragma unroll
    for (int nt = 0; nt < MAXNT; nt++) {
        if (nt >= ntCnt) break;
        const int n0 = (nt0 + nt) * 8;
        #pragma unroll
        for (int mt = 0; mt < 2; mt++) {
            const int r0 = mbase + mt * 16 + grp;
            __half2 v0 = __floats2half2_rn(fmaxf(acc[nt][mt][0], 0.f), fmaxf(acc[nt][mt][1], 0.f));
            __half2 v1 = __floats2half2_rn(fmaxf(acc[nt][mt][2], 0.f), fmaxf(acc[nt][mt][3], 0.f));
            *(__half2*)(Hout + r0 * sOut + n0 + 2 * tig) = v0;
            *(__half2*)(Hout + (r0 + 8) * sOut + n0 + 2 * tig) = v1;
        }
    }
}

// Layer 4 (100->256, no relu) with fused einsum epilogue into MSG (smem atomics).
__device__ __forceinline__ void layer4_f16(
    const __half* __restrict__ Hin,
    const __half* __restrict__ W4h,
    const float* __restrict__ b4f,
    const float* __restrict__ XV,
    float* __restrict__ MSG,
    int q, int mbase, int lane)
{
    const int grp = lane >> 2, tig = lane & 3;
    float acc[8][2][4];
    #pragma unroll
    for (int nt = 0; nt < 8; nt++) {
        const int c = (q * 8 + nt) * 8 + 2 * tig;
        const float b0 = b4f[c], b1 = b4f[c + 1];
        #pragma unroll
        for (int mt = 0; mt < 2; mt++) {
            acc[nt][mt][0] = b0; acc[nt][mt][1] = b1;
            acc[nt][mt][2] = b0; acc[nt][mt][3] = b1;
        }
    }
    const int arow = mbase + ((lane >> 3) & 1) * 8 + (lane & 7);
    const int acol = (lane >> 4) * 8;
    const int brow = lane & 15;
    #pragma unroll
    for (int k = 0; k < 7; k++) {
        const int k0 = k * 16;
        uint32_t a[2][4];
        #pragma unroll
        for (int mt = 0; mt < 2; mt++) {
            uint32_t aaddr = smem_u32(Hin + (arow + mt * 16) * 120 + k0 + acol);
            LDSM_X4(a[mt], aaddr);
        }
        #pragma unroll
        for (int nt = 0; nt < 8; nt++) {
            const int n0 = (q * 8 + nt) * 8;
            uint32_t b[2];
            uint32_t baddr = smem_u32(W4h + (k0 + brow) * 264 + n0);
            LDSM_X2T(b, baddr);
            MMA16816(acc[nt][0], a[0], b);
            MMA16816(acc[nt][1], a[1], b);
        }
    }
    #pragma unroll
    for (int nt = 0; nt < 8; nt++) {
        const int c = (q * 8 + nt) * 8 + 2 * tig;   // even
        const int i = c >> 4, o = c & 15;
        #pragma unroll
        for (int mt = 0; mt < 2; mt++) {
            const int e0 = mbase + mt * 16 + grp, e1 = e0 + 8;
            const float xv0 = XV[e0 * 16 + i], xv1 = XV[e1 * 16 + i];
            atomicAdd(&MSG[e0 * 16 + o],     xv0 * acc[nt][mt][0]);
            atomicAdd(&MSG[e0 * 16 + o + 1], xv0 * acc[nt][mt][1]);
            atomicAdd(&MSG[e1 * 16 + o],     xv1 * acc[nt][mt][2]);
            atomicAdd(&MSG[e1 * 16 + o + 1], xv1 * acc[nt][mt][3]);
        }
    }
}

extern __shared__ char smem[];

__global__ void __launch_bounds__(THREADS, 1)
edge_kernel(const float* __restrict__ x,
            const int* __restrict__ ei,
            const float* __restrict__ ea,
            const float* __restrict__ W1, const float* __restrict__ b1,
            const float* __restrict__ W2, const float* __restrict__ b2,
            const float* __restrict__ W3, const float* __restrict__ b3,
            const float* __restrict__ W4, const float* __restrict__ b4)
{
    const int tid = threadIdx.x;
    const int wid = tid >> 5, lane = tid & 31;
    const int q = wid & 3, mbase = (wid >> 2) * 32;

    __half* W1h = (__half*)(smem + SM_W1);
    __half* W2h = (__half*)(smem + SM_W2);
    __half* W3h = (__half*)(smem + SM_W3);
    __half* W4h = (__half*)(smem + SM_W4);
    __half* A0h = (__half*)(smem + SM_A0);
    __half* H1h = (__half*)(smem + SM_H1);
    __half* H2h = (__half*)(smem + SM_H2);
    float*  XV  = (float*)(smem + SM_XV);
    float*  MSG = (float*)(smem + SM_MSG);
    float*  B1f = (float*)(smem + SM_B1);
    float*  B2f = (float*)(smem + SM_B2);
    float*  B3f = (float*)(smem + SM_B3);
    float*  B4f = (float*)(smem + SM_B4);
    int*    DSTi = (int*)(smem + SM_IDX);
    int*    SRCi = (int*)(smem + SM_SRC);

    // zero weight region (covers K/N zero-padding)
    for (int i = tid; i < W_ZERO_U32; i += THREADS) ((uint32_t*)smem)[i] = 0;
    __syncthreads();
    for (int i = tid; i < 8 * 100; i += THREADS) {
        int k = i / 100, n = i % 100;
        W1h[k * 120 + n] = __float2half(W1[i]);
    }
    for (int i = tid; i < 100 * 100; i += THREADS) {
        int k = i / 100, n = i % 100;
        W2h[k * 120 + n] = __float2half(W2[i]);
        W3h[k * 120 + n] = __float2half(W3[i]);
    }
    for (int i = tid; i < 100 * 256; i += THREADS) {
        int k = i >> 8, n = i & 255;
        W4h[k * 264 + n] = __float2half(W4[i]);
    }
    for (int i = tid; i < 112; i += THREADS) {
        B1f[i] = (i < 100) ? b1[i] : 0.0f;
        B2f[i] = (i < 100) ? b2[i] : 0.0f;
        B3f[i] = (i < 100) ? b3[i] : 0.0f;
    }
    for (int i = tid; i < 256; i += THREADS) B4f[i] = b4[i];
    __syncthreads();

    static const int nt0s[4]  = {0, 4, 8, 11};
    static const int ntcs[4]  = {4, 4, 3, 3};
    const int nt0 = nt0s[q], ntc = ntcs[q];

    for (int t = blockIdx.x; t < NT_TILES; t += GRID) {
        const int base = t * M_TILE;
        if (tid < 64) {
            SRCi[tid] = ei[base + tid];
            DSTi[tid] = ei[N_EDGES + base + tid];
        }
        for (int i = tid; i < 64 * 16; i += THREADS) {
            int e = i >> 4, k = i & 15;
            A0h[e * 24 + k] = (k < 8) ? __float2half(ea[(base + e) * 8 + k]) : __half(0.0f);
        }
        for (int i = tid; i < 1024; i += THREADS) MSG[i] = 0.0f;
        __syncthreads();

        // gather x[src] (float4 per thread)
        {
            int e = tid >> 2, c4 = tid & 3;
            ((float4*)XV)[tid] = ((const float4*)x)[SRCi[e] * 4 + c4];
        }

        layer_f16<1, 4>(A0h, 24,  W1h, 120, B1f, H1h, 120, nt0, ntc, mbase, lane);
        __syncthreads();
        layer_f16<7, 4>(H1h, 120, W2h, 120, B2f, H2h, 120, nt0, ntc, mbase, lane);
        __syncthreads();
        layer_f16<7, 4>(H2h, 120, W3h, 120, B3f, H1h, 120, nt0, ntc, mbase, lane);
        __syncthreads();
        layer4_f16(H1h, W4h, B4f, XV, MSG, q, mbase, lane);
        __syncthreads();

        for (int i = tid; i < 1024; i += THREADS) {
            int e = i >> 4, o = i & 15;
            atomicAdd(&g_agg[(long)DSTi[e] * OUT_CH + o], MSG[i]);
        }
        if (tid < 64) atomicAdd(&g_cnt[DSTi[tid]], 1.0f);
        __syncthreads();
    }
}

__global__ void finalize_kernel(const float* __restrict__ x,
                                const float* __restrict__ root,
                                const float* __restrict__ bias,
                                float* __restrict__ out)
{
    int i = blockIdx.x * blockDim.x + threadIdx.x;
    if (i >= N_NODES * OUT_CH) return;
    int n = i >> 4, o = i & 15;
    float c = fmaxf(g_cnt[n], 1.0f);
    float acc = g_agg[i] / c + bias[o];
    const float* xr = x + (long)n * IN_CH;
    #pragma unroll
    for (int k = 0; k < IN_CH; k++)
        acc += xr[k] * root[k * OUT_CH + o];
    out[i] = acc;
}

extern "C" void kernel_launch(void* const* d_in, const int* in_sizes, int n_in,
                              void* d_out, int out_size) {
    const float* x    = (const float*)d_in[0];
    const int*   ei   = (const int*)d_in[1];
    const float* ea   = (const float*)d_in[2];
    const float* W1   = (const float*)d_in[3];
    const float* b1   = (const float*)d_in[4];
    const float* W2   = (const float*)d_in[5];
    const float* b2   = (const float*)d_in[6];
    const float* W3   = (const float*)d_in[7];
    const float* b3   = (const float*)d_in[8];
    const float* W4   = (const float*)d_in[9];
    const float* b4   = (const float*)d_in[10];
    const float* root = (const float*)d_in[11];
    const float* bias = (const float*)d_in[12];
    float* out = (float*)d_out;

    cudaFuncSetAttribute(edge_kernel, cudaFuncAttributeMaxDynamicSharedMemorySize, SMEM_BYTES);

    zero_kernel<<<1024, 256>>>();
    edge_kernel<<<GRID, THREADS, SMEM_BYTES>>>(x, ei, ea, W1, b1, W2, b2, W3, b3, W4, b4);
    finalize_kernel<<<(N_NODES * OUT_CH + 255) / 256, 256>>>(x, root, bias, out);
}